// round 15
// baseline (speedup 1.0000x reference)
#include <cuda_runtime.h>

// ---------------- problem constants ----------------
#define NSTEP 99          // T-1 sequential steps
#define B 256
#define D 700
#define H 1024
#define O 20
#define ALPHAC 0.9512294245007140f   // exp(-1/20)
#define KAPPAC 0.9512294245007140f
#define THRC   1.0f

#define ZSTR  20          // padded batch stride (floats) in shared z tile
#define WCHUNK 64         // j per staged w chunk
#define NCHUNK 16         // 1024 / 64
// smem: zs 1024*ZSTR floats (80KB) + wdup 2 * 64*256 floats (128KB)
#define FUSED_SMEM ((1024 * ZSTR + 2 * WCHUNK * 256) * 4)   // 212992 B

typedef unsigned long long ull;

// ---------------- device scratch (static; no allocations) ----------------
__device__ float g_xin[NSTEP * B * H];   // precomputed x @ w_in^T  (~104 MB)
__device__ float g_wt[H * H];            // w_rec^T with zeroed diagonal
__device__ float g_v[B * H];             // membrane potential
__device__ float g_z[2][B * H];          // spikes, double-buffered
__device__ float g_vo[B * O];            // output filter state

// ---------------- packed fp32x2 helpers ----------------
__device__ __forceinline__ ull fma2(ull a, ull b, ull c) {
    ull d;
    asm("fma.rn.f32x2 %0, %1, %2, %3;" : "=l"(d) : "l"(a), "l"(b), "l"(c));
    return d;
}
__device__ __forceinline__ ull add2(ull a, ull b) {
    ull d;
    asm("add.rn.f32x2 %0, %1, %2;" : "=l"(d) : "l"(a), "l"(b));
    return d;
}
__device__ __forceinline__ ull pack2(float x, float y) {
    ull d;
    asm("mov.b64 %0, {%1, %2};" : "=l"(d) : "f"(x), "f"(y));
    return d;
}
__device__ __forceinline__ float2 unpack2(ull a) {
    float2 r;
    asm("mov.b64 {%0, %1}, %2;" : "=f"(r.x), "=f"(r.y) : "l"(a));
    return r;
}

// v_n = (((alpha*v) + dot_rec) + xin) - z   [no contraction, left-assoc]
__device__ __forceinline__ float v_update(float v, float dot_rec, float xin, float z) {
    float t = __fmul_rn(ALPHAC, v);
    t = __fadd_rn(t, dot_rec);
    t = __fadd_rn(t, xin);
    t = __fsub_rn(t, z);
    return t;
}

// ---------------- init ----------------
__global__ void k_init(float* __restrict__ out) {
    int idx = blockIdx.x * 256 + threadIdx.x;
    if (idx < B * H) {
        g_v[idx] = 0.0f;
        g_z[0][idx] = 0.0f;
    }
    if (idx < B * O) {
        g_vo[idx] = 0.0f;
        out[idx] = 1.0f / (float)O;   // softmax(0) = 1/O
    }
}

// ---------------- prep: w_rec^T with zero diagonal ----------------
__global__ void k_prep_wt(const float* __restrict__ w_rec) {
    __shared__ float tile[32][33];
    int bx = blockIdx.x * 32, by = blockIdx.y * 32;
    int tx = threadIdx.x, ty = threadIdx.y;
    tile[ty][tx] = w_rec[(by + ty) * H + bx + tx];
    __syncthreads();
    int j = bx + ty, i = by + tx;
    float val = tile[tx][ty];                        // = w_rec[i][j]
    if (i == j) val = 0.0f;
    g_wt[j * H + i] = val;
}

// ---------------- input GEMM: kc=400 panels, single launch ------------------
// run[m][n] = p0 + p1,  p0 = ascending chain over [0,400), p1 over [400,700)
// (trailing zero-pad to 704 is exact). p0 stashed in smem between panels.
#define BM 128
#define BN 128
#define BK 8
__global__ void __launch_bounds__(256) k_gemm(const float* __restrict__ X,
                                              const float* __restrict__ Win) {
    extern __shared__ ull stash[];   // 256 * 32 ull = 64 KB
    __shared__ __align__(16) float As[BK][BM];
    __shared__ __align__(16) float Bs[BK][BN];
    int m0 = blockIdx.y * BM;
    int n0 = blockIdx.x * BN;
    int tid = threadIdx.x;
    int ty = tid >> 4, tx = tid & 15;
    int tm = ty * 8, tn = tx * 8;
    int srow = tid >> 1;
    int scol = (tid & 1) * 4;

    ull c[8][4];
#pragma unroll
    for (int i = 0; i < 8; i++)
#pragma unroll
        for (int p = 0; p < 4; p++) c[i][p] = 0ull;

    auto tile = [&](int k0) {
        {
            int gk = k0 + scol;
            float4 va, vb;
            const float* ap = X + (m0 + srow) * D + gk;
            const float* bp = Win + (n0 + srow) * D + gk;
            if (gk + 3 < D) {
                va = *(const float4*)ap;
                vb = *(const float4*)bp;
            } else {
                va.x = (gk + 0 < D) ? ap[0] : 0.0f;
                va.y = (gk + 1 < D) ? ap[1] : 0.0f;
                va.z = (gk + 2 < D) ? ap[2] : 0.0f;
                va.w = (gk + 3 < D) ? ap[3] : 0.0f;
                vb.x = (gk + 0 < D) ? bp[0] : 0.0f;
                vb.y = (gk + 1 < D) ? bp[1] : 0.0f;
                vb.z = (gk + 2 < D) ? bp[2] : 0.0f;
                vb.w = (gk + 3 < D) ? bp[3] : 0.0f;
            }
            As[scol + 0][srow] = va.x; As[scol + 1][srow] = va.y;
            As[scol + 2][srow] = va.z; As[scol + 3][srow] = va.w;
            Bs[scol + 0][srow] = vb.x; Bs[scol + 1][srow] = vb.y;
            Bs[scol + 2][srow] = vb.z; Bs[scol + 3][srow] = vb.w;
        }
        __syncthreads();
#pragma unroll
        for (int k = 0; k < BK; k++) {
            float4 a0 = *(const float4*)&As[k][tm];
            float4 a1 = *(const float4*)&As[k][tm + 4];
            const ull* bp2 = (const ull*)&Bs[k][tn];
            ull b2[4];
#pragma unroll
            for (int p = 0; p < 4; p++) b2[p] = bp2[p];
            float a[8] = {a0.x, a0.y, a0.z, a0.w, a1.x, a1.y, a1.z, a1.w};
#pragma unroll
            for (int i = 0; i < 8; i++) {
                ull ap2 = pack2(a[i], a[i]);
#pragma unroll
                for (int p = 0; p < 4; p++) c[i][p] = fma2(ap2, b2[p], c[i][p]);
            }
        }
        __syncthreads();
    };

    // panel 0: [0, 400)
    for (int k0 = 0; k0 < 400; k0 += BK) tile(k0);
#pragma unroll
    for (int i = 0; i < 8; i++)
#pragma unroll
        for (int p = 0; p < 4; p++) {
            stash[(i * 4 + p) * 256 + tid] = c[i][p];
            c[i][p] = 0ull;
        }
    // panel 1: [400, 704)  (700..703 zero-padded, exact)
    for (int k0 = 400; k0 < 704; k0 += BK) tile(k0);

    int gm = m0 + tm, gn = n0 + tn;
#pragma unroll
    for (int i = 0; i < 8; i++) {
        ull r[4];
#pragma unroll
        for (int p = 0; p < 4; p++)
            r[p] = add2(stash[(i * 4 + p) * 256 + tid], c[i][p]);
        float2 r0 = unpack2(r[0]);
        float2 r1 = unpack2(r[1]);
        float2 r2 = unpack2(r[2]);
        float2 r3 = unpack2(r[3]);
        float4 v0 = make_float4(r0.x, r0.y, r1.x, r1.y);
        float4 v1 = make_float4(r2.x, r2.y, r3.x, r3.y);
        *(float4*)&g_xin[(gm + i) * H + gn] = v0;
        *(float4*)&g_xin[(gm + i) * H + gn + 4] = v1;
    }
}

// ---------------- fused per-timestep kernel --------------------------------
// Launch s = 0..99, grid = 128 blocks x 256 threads (1 wave).
// Block bx: step (i-chunk bx&7, batch-group bx>>3) if s<99;
//           readout of output row s for batches {2bx, 2bx+1} if s>=1.
// Recurrent dot: kc=400 panels, ascending chains, left-assoc combine —
// identical arithmetic to rounds 13/14. w staged as DUPLICATED pairs
// (w_i,w_i,w_{i+1},w_{i+1}) in smem via LDG->regs->STS double buffer, so the
// inner loop is LDS.128(w) + LDS.128(z) + 4 FFMA2 with no MOV duplication.
__global__ void __launch_bounds__(256) k_fused(int s, const float* __restrict__ Wout,
                                               float* __restrict__ out) {
    extern __shared__ float dsm[];
    float* zs = dsm;                        // 1024*ZSTR floats (80 KB)
    float* wdup = dsm + 1024 * ZSTR;        // 2 * 64*256 floats (128 KB)
    __shared__ float svo[2][O];
    __shared__ float sv2[2][O];

    int tid = threadIdx.x;
    int bx = blockIdx.x;
    int ib = bx & 7, gb = bx >> 3;
    int i0 = ib * 128, b0 = gb * 16;

    const float* __restrict__ zprev = g_z[s & 1];
    float* __restrict__ znew = g_z[(s + 1) & 1];
    bool do_step = (s < NSTEP);

    float4 rg[8];   // staged w rows for next chunk (8 float4 = 32 floats)

    if (do_step) {
        // LDG chunk 0 into registers (latency hidden by z staging + readout)
#pragma unroll
        for (int u = 0; u < 8; u++) {
            int unit = u * 256 + tid;
            int jl = unit >> 5, cc = unit & 31;
            rg[u] = *(const float4*)&g_wt[jl * H + i0 + cc * 4];
        }
        // stage z for this block's 16 batches: zs[j*ZSTR + nb]
        for (int idx = tid; idx < 16 * 1024; idx += 256) {
            int nb = idx >> 10, j = idx & 1023;
            zs[j * ZSTR + nb] = zprev[(b0 + nb) * H + j];
        }
    }

    if (s >= 1) {
        // readout for batches 2bx (threads 0-127) and 2bx+1 (threads 128-255)
        int h = tid >> 7;
        int rb = 2 * bx + h;
        int lt = tid & 127;
        int lane = lt & 31, w4 = lt >> 5;
        float zr[32];
#pragma unroll
        for (int q = 0; q < 32; q++) zr[q] = zprev[rb * H + lane + q * 32];
#pragma unroll
        for (int oo = 0; oo < 5; oo++) {
            int o = w4 * 5 + oo;
            float sum = 0.0f;
#pragma unroll
            for (int q = 0; q < 32; q++)
                sum = __fmaf_rn(zr[q], Wout[o * H + lane + q * 32], sum);
#pragma unroll
            for (int off = 16; off; off >>= 1) sum += __shfl_xor_sync(0xffffffffu, sum, off);
            if (lane == 0) svo[h][o] = sum;
        }
        __syncthreads();
        if (lt < O) {
            float vo = __fadd_rn(__fmul_rn(KAPPAC, g_vo[rb * O + lt]), svo[h][lt]);
            g_vo[rb * O + lt] = vo;
            sv2[h][lt] = vo;
        }
        __syncthreads();
        if (lt < O) {
            float m = -1e30f;
#pragma unroll
            for (int j = 0; j < O; j++) m = fmaxf(m, sv2[h][j]);
            float e = expf(sv2[h][lt] - m);
            float ss = 0.0f;
#pragma unroll
            for (int j = 0; j < O; j++) ss += expf(sv2[h][j] - m);
            out[(s * B + rb) * O + lt] = e / ss;
        }
    }

    if (!do_step) return;
    __syncthreads();   // z staging visible

    int pi = tid & 63, qt = tid >> 6;
    int ia = i0 + 2 * pi;   // this thread: neurons ia, ia+1; batches qt*4..qt*4+3

    ull r00 = 0, r01 = 0, r10 = 0, r11 = 0;   // panel-combined runs
    ull a00 = 0, a01 = 0, a10 = 0, a11 = 0;   // current panel accumulators

#define STEP_BODY(JL) {                                                        \
        ulonglong2 wq = *(const ulonglong2*)(wp + (JL) * 256 + 4 * pi);        \
        ulonglong2 zq = *(const ulonglong2*)(zs + (jb + (JL)) * ZSTR + qt * 4);\
        a00 = fma2(zq.x, wq.x, a00); a01 = fma2(zq.y, wq.x, a01);              \
        a10 = fma2(zq.x, wq.y, a10); a11 = fma2(zq.y, wq.y, a11);              \
    }

    for (int c = 0; c < NCHUNK; c++) {
        // STS: write duplicated pairs for chunk c into buffer c&1
        float* wd = wdup + (c & 1) * (WCHUNK * 256);
#pragma unroll
        for (int u = 0; u < 8; u++) {
            int unit = u * 256 + tid;
            int jl = unit >> 5, cc = unit & 31;
            float4 v = rg[u];
            float* d = wd + jl * 256 + cc * 8;
            *(float4*)(d)     = make_float4(v.x, v.x, v.y, v.y);
            *(float4*)(d + 4) = make_float4(v.z, v.z, v.w, v.w);
        }
        __syncthreads();
        // LDG: next chunk into registers (latency hidden by compute below)
        if (c + 1 < NCHUNK) {
#pragma unroll
            for (int u = 0; u < 8; u++) {
                int unit = u * 256 + tid;
                int jl = unit >> 5, cc = unit & 31;
                rg[u] = *(const float4*)&g_wt[((c + 1) * WCHUNK + jl) * H + i0 + cc * 4];
            }
        }
        const float* wp = wd;
        int jb = c * WCHUNK;
        // panel boundaries: j=400 in chunk 6 (jl 16), j=800 in chunk 12 (jl 32)
        int bjl = (c == 6) ? 16 : (c == 12) ? 32 : 64;
#pragma unroll 8
        for (int jl = 0; jl < bjl; jl++) STEP_BODY(jl);
        if (bjl < 64) {
            // panel flush
            r00 = add2(r00, a00); r01 = add2(r01, a01);
            r10 = add2(r10, a10); r11 = add2(r11, a11);
            a00 = 0; a01 = 0; a10 = 0; a11 = 0;
#pragma unroll 8
            for (int jl = bjl; jl < 64; jl++) STEP_BODY(jl);
        }
        __syncthreads();
    }
#undef STEP_BODY
    // final panel flush
    r00 = add2(r00, a00); r01 = add2(r01, a01);
    r10 = add2(r10, a10); r11 = add2(r11, a11);

    const float* xin_t = g_xin + s * (B * H);
    ull rr[2][2] = {{r00, r01}, {r10, r11}};
#pragma unroll
    for (int n = 0; n < 2; n++) {
        int i = ia + n;
#pragma unroll
        for (int q = 0; q < 2; q++) {
            float2 r = unpack2(rr[n][q]);
            int b = b0 + qt * 4 + 2 * q;
            float zp0 = zs[i * ZSTR + qt * 4 + 2 * q];
            float zp1 = zs[i * ZSTR + qt * 4 + 2 * q + 1];
            float v0 = v_update(g_v[b * H + i], r.x, xin_t[b * H + i], zp0);
            float v1 = v_update(g_v[(b + 1) * H + i], r.y, xin_t[(b + 1) * H + i], zp1);
            g_v[b * H + i] = v0;
            g_v[(b + 1) * H + i] = v1;
            znew[b * H + i] = (v0 > THRC) ? 1.0f : 0.0f;
            znew[(b + 1) * H + i] = (v1 > THRC) ? 1.0f : 0.0f;
        }
    }
}

// ---------------- launch ----------------
extern "C" void kernel_launch(void* const* d_in, const int* in_sizes, int n_in,
                              void* d_out, int out_size) {
    const float* x     = (const float*)d_in[0];   // [T, B, D]
    const float* w_in  = (const float*)d_in[1];   // [H, D]
    const float* w_rec = (const float*)d_in[2];   // [H, H]
    const float* w_out = (const float*)d_in[3];   // [O, H]
    float* out = (float*)d_out;                   // [T, B, O]

    cudaFuncSetAttribute(k_fused, cudaFuncAttributeMaxDynamicSharedMemorySize, FUSED_SMEM);
    cudaFuncSetAttribute(k_gemm, cudaFuncAttributeMaxDynamicSharedMemorySize, 65536);

    k_init<<<(B * H + 255) / 256, 256>>>(out);
    k_prep_wt<<<dim3(H / 32, H / 32), dim3(32, 32)>>>(w_rec);
    // input GEMM: kc=400 panels, single launch (p0 stashed in smem)
    k_gemm<<<dim3(H / BN, (NSTEP * B) / BM), 256, 65536>>>(x, w_in);

    for (int s = 0; s <= NSTEP; s++) {
        k_fused<<<128, 256, FUSED_SMEM>>>(s, w_out, out);
    }
}

// round 16
// speedup vs baseline: 1.0081x; 1.0081x over previous
#include <cuda_runtime.h>

// ---------------- problem constants ----------------
#define NSTEP 99          // T-1 sequential steps
#define B 256
#define D 700
#define H 1024
#define O 20
#define ALPHAC 0.9512294245007140f   // exp(-1/20)
#define KAPPAC 0.9512294245007140f
#define THRC   1.0f

#define ZSTR  20          // padded batch stride (floats) in shared z tile
#define WCHUNK 64         // j per staged w chunk
#define NCHUNK 16         // 1024 / 64
// smem: zs 1024*ZSTR floats (80KB) + wdup 2 * 64*256 floats (128KB)
#define FUSED_SMEM ((1024 * ZSTR + 2 * WCHUNK * 256) * 4)   // 212992 B

typedef unsigned long long ull;

// ---------------- device scratch (static; no allocations) ----------------
__device__ float g_xin[NSTEP * B * H];   // precomputed x @ w_in^T  (~104 MB)
__device__ float g_wt[H * H];            // w_rec^T with zeroed diagonal
__device__ float g_v[B * H];             // membrane potential
__device__ float g_z[2][B * H];          // spikes, double-buffered
__device__ float g_vo[B * O];            // output filter state

// ---------------- packed fp32x2 helpers ----------------
__device__ __forceinline__ ull fma2(ull a, ull b, ull c) {
    ull d;
    asm("fma.rn.f32x2 %0, %1, %2, %3;" : "=l"(d) : "l"(a), "l"(b), "l"(c));
    return d;
}
__device__ __forceinline__ ull add2(ull a, ull b) {
    ull d;
    asm("add.rn.f32x2 %0, %1, %2;" : "=l"(d) : "l"(a), "l"(b));
    return d;
}
__device__ __forceinline__ ull pack2(float x, float y) {
    ull d;
    asm("mov.b64 %0, {%1, %2};" : "=l"(d) : "f"(x), "f"(y));
    return d;
}
__device__ __forceinline__ float2 unpack2(ull a) {
    float2 r;
    asm("mov.b64 {%0, %1}, %2;" : "=f"(r.x), "=f"(r.y) : "l"(a));
    return r;
}

// v_n = (((alpha*v) + dot_rec) + xin) - z   [no contraction, left-assoc]
__device__ __forceinline__ float v_update(float v, float dot_rec, float xin, float z) {
    float t = __fmul_rn(ALPHAC, v);
    t = __fadd_rn(t, dot_rec);
    t = __fadd_rn(t, xin);
    t = __fsub_rn(t, z);
    return t;
}

// ---------------- init ----------------
__global__ void k_init(float* __restrict__ out) {
    int idx = blockIdx.x * 256 + threadIdx.x;
    if (idx < B * H) {
        g_v[idx] = 0.0f;
        g_z[0][idx] = 0.0f;
    }
    if (idx < B * O) {
        g_vo[idx] = 0.0f;
        out[idx] = 1.0f / (float)O;   // softmax(0) = 1/O
    }
}

// ---------------- prep: w_rec^T with zero diagonal ----------------
__global__ void k_prep_wt(const float* __restrict__ w_rec) {
    __shared__ float tile[32][33];
    int bx = blockIdx.x * 32, by = blockIdx.y * 32;
    int tx = threadIdx.x, ty = threadIdx.y;
    tile[ty][tx] = w_rec[(by + ty) * H + bx + tx];
    __syncthreads();
    int j = bx + ty, i = by + tx;
    float val = tile[tx][ty];                        // = w_rec[i][j]
    if (i == j) val = 0.0f;
    g_wt[j * H + i] = val;
}

// ---------------- input GEMM: kc=400 panels, single launch ------------------
// run[m][n] = p0 + p1,  p0 = ascending chain over [0,400), p1 over [400,700)
// (trailing zero-pad to 704 is exact). p0 stashed in smem between panels.
#define BM 128
#define BN 128
#define BK 8
__global__ void __launch_bounds__(256) k_gemm(const float* __restrict__ X,
                                              const float* __restrict__ Win) {
    extern __shared__ ull stash[];   // 256 * 32 ull = 64 KB
    __shared__ __align__(16) float As[BK][BM];
    __shared__ __align__(16) float Bs[BK][BN];
    int m0 = blockIdx.y * BM;
    int n0 = blockIdx.x * BN;
    int tid = threadIdx.x;
    int ty = tid >> 4, tx = tid & 15;
    int tm = ty * 8, tn = tx * 8;
    int srow = tid >> 1;
    int scol = (tid & 1) * 4;

    ull c[8][4];
#pragma unroll
    for (int i = 0; i < 8; i++)
#pragma unroll
        for (int p = 0; p < 4; p++) c[i][p] = 0ull;

    auto tile = [&](int k0) {
        {
            int gk = k0 + scol;
            float4 va, vb;
            const float* ap = X + (m0 + srow) * D + gk;
            const float* bp = Win + (n0 + srow) * D + gk;
            if (gk + 3 < D) {
                va = *(const float4*)ap;
                vb = *(const float4*)bp;
            } else {
                va.x = (gk + 0 < D) ? ap[0] : 0.0f;
                va.y = (gk + 1 < D) ? ap[1] : 0.0f;
                va.z = (gk + 2 < D) ? ap[2] : 0.0f;
                va.w = (gk + 3 < D) ? ap[3] : 0.0f;
                vb.x = (gk + 0 < D) ? bp[0] : 0.0f;
                vb.y = (gk + 1 < D) ? bp[1] : 0.0f;
                vb.z = (gk + 2 < D) ? bp[2] : 0.0f;
                vb.w = (gk + 3 < D) ? bp[3] : 0.0f;
            }
            As[scol + 0][srow] = va.x; As[scol + 1][srow] = va.y;
            As[scol + 2][srow] = va.z; As[scol + 3][srow] = va.w;
            Bs[scol + 0][srow] = vb.x; Bs[scol + 1][srow] = vb.y;
            Bs[scol + 2][srow] = vb.z; Bs[scol + 3][srow] = vb.w;
        }
        __syncthreads();
#pragma unroll
        for (int k = 0; k < BK; k++) {
            float4 a0 = *(const float4*)&As[k][tm];
            float4 a1 = *(const float4*)&As[k][tm + 4];
            const ull* bp2 = (const ull*)&Bs[k][tn];
            ull b2[4];
#pragma unroll
            for (int p = 0; p < 4; p++) b2[p] = bp2[p];
            float a[8] = {a0.x, a0.y, a0.z, a0.w, a1.x, a1.y, a1.z, a1.w};
#pragma unroll
            for (int i = 0; i < 8; i++) {
                ull ap2 = pack2(a[i], a[i]);
#pragma unroll
                for (int p = 0; p < 4; p++) c[i][p] = fma2(ap2, b2[p], c[i][p]);
            }
        }
        __syncthreads();
    };

    // panel 0: [0, 400)
    for (int k0 = 0; k0 < 400; k0 += BK) tile(k0);
#pragma unroll
    for (int i = 0; i < 8; i++)
#pragma unroll
        for (int p = 0; p < 4; p++) {
            stash[(i * 4 + p) * 256 + tid] = c[i][p];
            c[i][p] = 0ull;
        }
    // panel 1: [400, 704)  (700..703 zero-padded, exact)
    for (int k0 = 400; k0 < 704; k0 += BK) tile(k0);

    int gm = m0 + tm, gn = n0 + tn;
#pragma unroll
    for (int i = 0; i < 8; i++) {
        ull r[4];
#pragma unroll
        for (int p = 0; p < 4; p++)
            r[p] = add2(stash[(i * 4 + p) * 256 + tid], c[i][p]);
        float2 r0 = unpack2(r[0]);
        float2 r1 = unpack2(r[1]);
        float2 r2 = unpack2(r[2]);
        float2 r3 = unpack2(r[3]);
        float4 v0 = make_float4(r0.x, r0.y, r1.x, r1.y);
        float4 v1 = make_float4(r2.x, r2.y, r3.x, r3.y);
        *(float4*)&g_xin[(gm + i) * H + gn] = v0;
        *(float4*)&g_xin[(gm + i) * H + gn + 4] = v1;
    }
}

// ---------------- fused per-timestep kernel --------------------------------
// Launch s = 0..99, grid = 128 blocks x 256 threads (1 wave).
// Block bx: step (i-chunk bx&7, batch-group bx>>3) if s<99;
//           readout of output row s for batches {2bx, 2bx+1} if s>=1.
// Recurrent dot: kc=400 panels, ascending chains, left-assoc combine —
// identical arithmetic to rounds 13-15. w staged DUPLICATED in smem.
// Lane mapping pi=tid>>2, qt=tid&3: the 4 lanes sharing a pi broadcast the
// same 16B of wdup, so each warp's w read is 1 wavefront and the block reads
// w exactly once per j (fixes round-15's 4x smem re-read).
__global__ void __launch_bounds__(256) k_fused(int s, const float* __restrict__ Wout,
                                               float* __restrict__ out) {
    extern __shared__ float dsm[];
    float* zs = dsm;                        // 1024*ZSTR floats (80 KB)
    float* wdup = dsm + 1024 * ZSTR;        // 2 * 64*256 floats (128 KB)
    __shared__ float svo[2][O];
    __shared__ float sv2[2][O];

    int tid = threadIdx.x;
    int bx = blockIdx.x;
    int ib = bx & 7, gb = bx >> 3;
    int i0 = ib * 128, b0 = gb * 16;

    const float* __restrict__ zprev = g_z[s & 1];
    float* __restrict__ znew = g_z[(s + 1) & 1];
    bool do_step = (s < NSTEP);

    float4 rg[8];   // staged w rows for next chunk (8 float4 = 32 floats)

    if (do_step) {
        // LDG chunk 0 into registers (latency hidden by z staging + readout)
#pragma unroll
        for (int u = 0; u < 8; u++) {
            int unit = u * 256 + tid;
            int jl = unit >> 5, cc = unit & 31;
            rg[u] = *(const float4*)&g_wt[jl * H + i0 + cc * 4];
        }
        // stage z for this block's 16 batches: zs[j*ZSTR + nb]
        for (int idx = tid; idx < 16 * 1024; idx += 256) {
            int nb = idx >> 10, j = idx & 1023;
            zs[j * ZSTR + nb] = zprev[(b0 + nb) * H + j];
        }
    }

    if (s >= 1) {
        // readout for batches 2bx (threads 0-127) and 2bx+1 (threads 128-255)
        int h = tid >> 7;
        int rb = 2 * bx + h;
        int lt = tid & 127;
        int lane = lt & 31, w4 = lt >> 5;
        float zr[32];
#pragma unroll
        for (int q = 0; q < 32; q++) zr[q] = zprev[rb * H + lane + q * 32];
#pragma unroll
        for (int oo = 0; oo < 5; oo++) {
            int o = w4 * 5 + oo;
            float sum = 0.0f;
#pragma unroll
            for (int q = 0; q < 32; q++)
                sum = __fmaf_rn(zr[q], Wout[o * H + lane + q * 32], sum);
#pragma unroll
            for (int off = 16; off; off >>= 1) sum += __shfl_xor_sync(0xffffffffu, sum, off);
            if (lane == 0) svo[h][o] = sum;
        }
        __syncthreads();
        if (lt < O) {
            float vo = __fadd_rn(__fmul_rn(KAPPAC, g_vo[rb * O + lt]), svo[h][lt]);
            g_vo[rb * O + lt] = vo;
            sv2[h][lt] = vo;
        }
        __syncthreads();
        if (lt < O) {
            float m = -1e30f;
#pragma unroll
            for (int j = 0; j < O; j++) m = fmaxf(m, sv2[h][j]);
            float e = expf(sv2[h][lt] - m);
            float ss = 0.0f;
#pragma unroll
            for (int j = 0; j < O; j++) ss += expf(sv2[h][j] - m);
            out[(s * B + rb) * O + lt] = e / ss;
        }
    }

    if (!do_step) return;
    __syncthreads();   // z staging visible

    // broadcast-friendly mapping: 4 lanes per pi (same wdup address),
    // qt = tid&3 selects the batch quartet (z broadcast within those lanes)
    int pi = tid >> 2, qt = tid & 3;
    int ia = i0 + 2 * pi;   // this thread: neurons ia, ia+1; batches qt*4..qt*4+3

    ull r00 = 0, r01 = 0, r10 = 0, r11 = 0;   // panel-combined runs
    ull a00 = 0, a01 = 0, a10 = 0, a11 = 0;   // current panel accumulators

#define STEP_BODY(JL) {                                                        \
        ulonglong2 wq = *(const ulonglong2*)(wp + (JL) * 256 + 4 * pi);        \
        ulonglong2 zq = *(const ulonglong2*)(zs + (jb + (JL)) * ZSTR + qt * 4);\
        a00 = fma2(zq.x, wq.x, a00); a01 = fma2(zq.y, wq.x, a01);              \
        a10 = fma2(zq.x, wq.y, a10); a11 = fma2(zq.y, wq.y, a11);              \
    }

    for (int c = 0; c < NCHUNK; c++) {
        // STS: write duplicated pairs for chunk c into buffer c&1
        float* wd = wdup + (c & 1) * (WCHUNK * 256);
#pragma unroll
        for (int u = 0; u < 8; u++) {
            int unit = u * 256 + tid;
            int jl = unit >> 5, cc = unit & 31;
            float4 v = rg[u];
            float* d = wd + jl * 256 + cc * 8;
            *(float4*)(d)     = make_float4(v.x, v.x, v.y, v.y);
            *(float4*)(d + 4) = make_float4(v.z, v.z, v.w, v.w);
        }
        __syncthreads();
        // LDG: next chunk into registers (latency hidden by compute below)
        if (c + 1 < NCHUNK) {
#pragma unroll
            for (int u = 0; u < 8; u++) {
                int unit = u * 256 + tid;
                int jl = unit >> 5, cc = unit & 31;
                rg[u] = *(const float4*)&g_wt[((c + 1) * WCHUNK + jl) * H + i0 + cc * 4];
            }
        }
        const float* wp = wd;
        int jb = c * WCHUNK;
        // panel boundaries: j=400 in chunk 6 (jl 16), j=800 in chunk 12 (jl 32)
        int bjl = (c == 6) ? 16 : (c == 12) ? 32 : 64;
#pragma unroll 8
        for (int jl = 0; jl < bjl; jl++) STEP_BODY(jl);
        if (bjl < 64) {
            // panel flush
            r00 = add2(r00, a00); r01 = add2(r01, a01);
            r10 = add2(r10, a10); r11 = add2(r11, a11);
            a00 = 0; a01 = 0; a10 = 0; a11 = 0;
#pragma unroll 8
            for (int jl = bjl; jl < 64; jl++) STEP_BODY(jl);
        }
        __syncthreads();
    }
#undef STEP_BODY
    // final panel flush
    r00 = add2(r00, a00); r01 = add2(r01, a01);
    r10 = add2(r10, a10); r11 = add2(r11, a11);

    const float* xin_t = g_xin + s * (B * H);
    ull rr[2][2] = {{r00, r01}, {r10, r11}};
#pragma unroll
    for (int n = 0; n < 2; n++) {
        int i = ia + n;
#pragma unroll
        for (int q = 0; q < 2; q++) {
            float2 r = unpack2(rr[n][q]);
            int b = b0 + qt * 4 + 2 * q;
            float zp0 = zs[i * ZSTR + qt * 4 + 2 * q];
            float zp1 = zs[i * ZSTR + qt * 4 + 2 * q + 1];
            float v0 = v_update(g_v[b * H + i], r.x, xin_t[b * H + i], zp0);
            float v1 = v_update(g_v[(b + 1) * H + i], r.y, xin_t[(b + 1) * H + i], zp1);
            g_v[b * H + i] = v0;
            g_v[(b + 1) * H + i] = v1;
            znew[b * H + i] = (v0 > THRC) ? 1.0f : 0.0f;
            znew[(b + 1) * H + i] = (v1 > THRC) ? 1.0f : 0.0f;
        }
    }
}

// ---------------- launch ----------------
extern "C" void kernel_launch(void* const* d_in, const int* in_sizes, int n_in,
                              void* d_out, int out_size) {
    const float* x     = (const float*)d_in[0];   // [T, B, D]
    const float* w_in  = (const float*)d_in[1];   // [H, D]
    const float* w_rec = (const float*)d_in[2];   // [H, H]
    const float* w_out = (const float*)d_in[3];   // [O, H]
    float* out = (float*)d_out;                   // [T, B, O]

    cudaFuncSetAttribute(k_fused, cudaFuncAttributeMaxDynamicSharedMemorySize, FUSED_SMEM);
    cudaFuncSetAttribute(k_gemm, cudaFuncAttributeMaxDynamicSharedMemorySize, 65536);

    k_init<<<(B * H + 255) / 256, 256>>>(out);
    k_prep_wt<<<dim3(H / 32, H / 32), dim3(32, 32)>>>(w_rec);
    // input GEMM: kc=400 panels, single launch (p0 stashed in smem)
    k_gemm<<<dim3(H / BN, (NSTEP * B) / BM), 256, 65536>>>(x, w_in);

    for (int s = 0; s <= NSTEP; s++) {
        k_fused<<<128, 256, FUSED_SMEM>>>(s, w_out, out);
    }
}

// round 17
// speedup vs baseline: 1.4453x; 1.4337x over previous
#include <cuda_runtime.h>

// ---------------- problem constants ----------------
#define NSTEP 99          // T-1 sequential steps
#define B 256
#define D 700
#define H 1024
#define O 20
#define ALPHAC 0.9512294245007140f   // exp(-1/20)
#define KAPPAC 0.9512294245007140f
#define THRC   1.0f

#define ZSTR  20          // padded batch stride (floats) in shared z tile
// smem: zs 1024*ZSTR floats (80KB) + pacc 2*256*4 ull (16KB)
#define FUSED_SMEM (1024 * ZSTR * 4 + 2 * 256 * 4 * 8)   // 98304 B

typedef unsigned long long ull;

// ---------------- device scratch (static; no allocations) ----------------
__device__ float g_xin[NSTEP * B * H];   // precomputed x @ w_in^T  (~104 MB)
__device__ float g_wt[H * H];            // w_rec^T with zeroed diagonal
__device__ float g_v[B * H];             // membrane potential
__device__ float g_z[2][B * H];          // spikes, double-buffered
__device__ float g_vo[B * O];            // output filter state

// ---------------- packed fp32x2 helpers ----------------
__device__ __forceinline__ ull fma2(ull a, ull b, ull c) {
    ull d;
    asm("fma.rn.f32x2 %0, %1, %2, %3;" : "=l"(d) : "l"(a), "l"(b), "l"(c));
    return d;
}
__device__ __forceinline__ ull add2(ull a, ull b) {
    ull d;
    asm("add.rn.f32x2 %0, %1, %2;" : "=l"(d) : "l"(a), "l"(b));
    return d;
}
__device__ __forceinline__ ull pack2(float x, float y) {
    ull d;
    asm("mov.b64 %0, {%1, %2};" : "=l"(d) : "f"(x), "f"(y));
    return d;
}
__device__ __forceinline__ float2 unpack2(ull a) {
    float2 r;
    asm("mov.b64 {%0, %1}, %2;" : "=f"(r.x), "=f"(r.y) : "l"(a));
    return r;
}

// v_n = (((alpha*v) + dot_rec) + xin) - z   [no contraction, left-assoc]
__device__ __forceinline__ float v_update(float v, float dot_rec, float xin, float z) {
    float t = __fmul_rn(ALPHAC, v);
    t = __fadd_rn(t, dot_rec);
    t = __fadd_rn(t, xin);
    t = __fsub_rn(t, z);
    return t;
}

// ---------------- init ----------------
__global__ void k_init(float* __restrict__ out) {
    int idx = blockIdx.x * 256 + threadIdx.x;
    if (idx < B * H) {
        g_v[idx] = 0.0f;
        g_z[0][idx] = 0.0f;
    }
    if (idx < B * O) {
        g_vo[idx] = 0.0f;
        out[idx] = 1.0f / (float)O;   // softmax(0) = 1/O
    }
}

// ---------------- prep: w_rec^T with zero diagonal ----------------
__global__ void k_prep_wt(const float* __restrict__ w_rec) {
    __shared__ float tile[32][33];
    int bx = blockIdx.x * 32, by = blockIdx.y * 32;
    int tx = threadIdx.x, ty = threadIdx.y;
    tile[ty][tx] = w_rec[(by + ty) * H + bx + tx];
    __syncthreads();
    int j = bx + ty, i = by + tx;
    float val = tile[tx][ty];                        // = w_rec[i][j]
    if (i == j) val = 0.0f;
    g_wt[j * H + i] = val;
}

// ---------------- input GEMM: kc=400 panels, single launch ------------------
#define BM 128
#define BN 128
#define BK 8
__global__ void __launch_bounds__(256) k_gemm(const float* __restrict__ X,
                                              const float* __restrict__ Win) {
    extern __shared__ ull stash[];   // 256 * 32 ull = 64 KB
    __shared__ __align__(16) float As[BK][BM];
    __shared__ __align__(16) float Bs[BK][BN];
    int m0 = blockIdx.y * BM;
    int n0 = blockIdx.x * BN;
    int tid = threadIdx.x;
    int ty = tid >> 4, tx = tid & 15;
    int tm = ty * 8, tn = tx * 8;
    int srow = tid >> 1;
    int scol = (tid & 1) * 4;

    ull c[8][4];
#pragma unroll
    for (int i = 0; i < 8; i++)
#pragma unroll
        for (int p = 0; p < 4; p++) c[i][p] = 0ull;

    auto tile = [&](int k0) {
        {
            int gk = k0 + scol;
            float4 va, vb;
            const float* ap = X + (m0 + srow) * D + gk;
            const float* bp = Win + (n0 + srow) * D + gk;
            if (gk + 3 < D) {
                va = *(const float4*)ap;
                vb = *(const float4*)bp;
            } else {
                va.x = (gk + 0 < D) ? ap[0] : 0.0f;
                va.y = (gk + 1 < D) ? ap[1] : 0.0f;
                va.z = (gk + 2 < D) ? ap[2] : 0.0f;
                va.w = (gk + 3 < D) ? ap[3] : 0.0f;
                vb.x = (gk + 0 < D) ? bp[0] : 0.0f;
                vb.y = (gk + 1 < D) ? bp[1] : 0.0f;
                vb.z = (gk + 2 < D) ? bp[2] : 0.0f;
                vb.w = (gk + 3 < D) ? bp[3] : 0.0f;
            }
            As[scol + 0][srow] = va.x; As[scol + 1][srow] = va.y;
            As[scol + 2][srow] = va.z; As[scol + 3][srow] = va.w;
            Bs[scol + 0][srow] = vb.x; Bs[scol + 1][srow] = vb.y;
            Bs[scol + 2][srow] = vb.z; Bs[scol + 3][srow] = vb.w;
        }
        __syncthreads();
#pragma unroll
        for (int k = 0; k < BK; k++) {
            float4 a0 = *(const float4*)&As[k][tm];
            float4 a1 = *(const float4*)&As[k][tm + 4];
            const ull* bp2 = (const ull*)&Bs[k][tn];
            ull b2[4];
#pragma unroll
            for (int p = 0; p < 4; p++) b2[p] = bp2[p];
            float a[8] = {a0.x, a0.y, a0.z, a0.w, a1.x, a1.y, a1.z, a1.w};
#pragma unroll
            for (int i = 0; i < 8; i++) {
                ull ap2 = pack2(a[i], a[i]);
#pragma unroll
                for (int p = 0; p < 4; p++) c[i][p] = fma2(ap2, b2[p], c[i][p]);
            }
        }
        __syncthreads();
    };

    // panel 0: [0, 400)
    for (int k0 = 0; k0 < 400; k0 += BK) tile(k0);
#pragma unroll
    for (int i = 0; i < 8; i++)
#pragma unroll
        for (int p = 0; p < 4; p++) {
            stash[(i * 4 + p) * 256 + tid] = c[i][p];
            c[i][p] = 0ull;
        }
    // panel 1: [400, 704)  (700..703 zero-padded, exact)
    for (int k0 = 400; k0 < 704; k0 += BK) tile(k0);

    int gm = m0 + tm, gn = n0 + tn;
#pragma unroll
    for (int i = 0; i < 8; i++) {
        ull r[4];
#pragma unroll
        for (int p = 0; p < 4; p++)
            r[p] = add2(stash[(i * 4 + p) * 256 + tid], c[i][p]);
        float2 r0 = unpack2(r[0]);
        float2 r1 = unpack2(r[1]);
        float2 r2 = unpack2(r[2]);
        float2 r3 = unpack2(r[3]);
        float4 v0 = make_float4(r0.x, r0.y, r1.x, r1.y);
        float4 v1 = make_float4(r2.x, r2.y, r3.x, r3.y);
        *(float4*)&g_xin[(gm + i) * H + gn] = v0;
        *(float4*)&g_xin[(gm + i) * H + gn + 4] = v1;
    }
}

// ---------------- fused per-timestep kernel --------------------------------
// Launch s = 0..99, grid = 128 blocks x 768 threads (1 wave, 24 warps/SM).
// Block bx: step (i-chunk bx&7, batch-group bx>>3) if s<99;
//           readout of output row s for batches {2bx,2bx+1} (group 2) if s>=1.
// Recurrent dot: kc=400 panels [0,400)[400,800)[800,1024). Each 256-thread
// group computes ONE panel's ascending chains in parallel; combine
// r = (p0 + p1) + p2 by group 0 — bit-identical to rounds 13-16.
__global__ void __launch_bounds__(768) k_fused(int s, const float* __restrict__ Wout,
                                               float* __restrict__ out) {
    extern __shared__ float dsm[];
    float* zs = dsm;                          // 1024*ZSTR floats (80 KB)
    ull* pacc = (ull*)(dsm + 1024 * ZSTR);    // [2][256][4] ull (16 KB)
    __shared__ float svo[2][O];
    __shared__ float sv2[2][O];

    int tid = threadIdx.x;
    int bx = blockIdx.x;
    int ib = bx & 7, gb = bx >> 3;
    int i0 = ib * 128, b0 = gb * 16;

    const float* __restrict__ zprev = g_z[s & 1];
    float* __restrict__ znew = g_z[(s + 1) & 1];
    bool do_step = (s < NSTEP);

    int grp = tid >> 8;          // panel group 0,1,2
    int t = tid & 255;           // thread within group
    int pi = t >> 2, qt = t & 3;
    int ia = i0 + 2 * pi;        // neurons ia, ia+1; batches qt*4..qt*4+3

    if (do_step) {
        // stage z for this block's 16 batches: zs[j*ZSTR + nb]
        for (int idx = tid; idx < 16 * 1024; idx += 768) {
            int nb = idx >> 10, j = idx & 1023;
            zs[j * ZSTR + nb] = zprev[(b0 + nb) * H + j];
        }
    }
    __syncthreads();

    // ---- readout (group 2, before its short panel) ----
    if (grp == 2 && s >= 1) {
        int h = t >> 7;
        int rb = 2 * bx + h;
        int lt = t & 127;
        int lane = lt & 31, w4 = lt >> 5;
        float zr[32];
#pragma unroll
        for (int q = 0; q < 32; q++) zr[q] = zprev[rb * H + lane + q * 32];
#pragma unroll
        for (int oo = 0; oo < 5; oo++) {
            int o = w4 * 5 + oo;
            float sum = 0.0f;
#pragma unroll
            for (int q = 0; q < 32; q++)
                sum = __fmaf_rn(zr[q], Wout[o * H + lane + q * 32], sum);
#pragma unroll
            for (int off = 16; off; off >>= 1) sum += __shfl_xor_sync(0xffffffffu, sum, off);
            if (lane == 0) svo[h][o] = sum;
        }
        asm volatile("bar.sync 1, 256;" ::: "memory");
        if (t < 2 * O) {
            int hh = t / O, oo = t % O;
            int rb2 = 2 * bx + hh;
            float vo = __fadd_rn(__fmul_rn(KAPPAC, g_vo[rb2 * O + oo]), svo[hh][oo]);
            g_vo[rb2 * O + oo] = vo;
            sv2[hh][oo] = vo;
        }
        asm volatile("bar.sync 1, 256;" ::: "memory");
        if (t < 2 * O) {
            int hh = t / O, oo = t % O;
            int rb2 = 2 * bx + hh;
            float m = -1e30f;
#pragma unroll
            for (int j = 0; j < O; j++) m = fmaxf(m, sv2[hh][j]);
            float e = expf(sv2[hh][oo] - m);
            float ss = 0.0f;
#pragma unroll
            for (int j = 0; j < O; j++) ss += expf(sv2[hh][j] - m);
            out[(s * B + rb2) * O + oo] = e / ss;
        }
    }

    // ---- panel compute ----
    ull a00 = 0, a01 = 0, a10 = 0, a11 = 0;
    if (do_step) {
        int jlo = (grp == 0) ? 0 : (grp == 1) ? 400 : 800;
        int jhi = (grp == 0) ? 400 : (grp == 1) ? 800 : 1024;
        const float* wp = g_wt + ia;
#pragma unroll 8
        for (int j = jlo; j < jhi; j++) {
            float2 w2 = *(const float2*)(wp + j * H);          // LDG.64, coalesced
            ull wA = pack2(w2.x, w2.x);
            ull wB = pack2(w2.y, w2.y);
            ulonglong2 zq = *(const ulonglong2*)(zs + j * ZSTR + qt * 4);
            a00 = fma2(zq.x, wA, a00); a01 = fma2(zq.y, wA, a01);
            a10 = fma2(zq.x, wB, a10); a11 = fma2(zq.y, wB, a11);
        }
        if (grp > 0) {
            ull* pd = pacc + (grp - 1) * 1024 + t * 4;
            pd[0] = a00; pd[1] = a01; pd[2] = a10; pd[3] = a11;
        }
    }
    __syncthreads();

    // ---- combine + epilogue (group 0) ----
    if (do_step && grp == 0) {
        const ull* p1 = pacc + t * 4;
        const ull* p2 = pacc + 1024 + t * 4;
        ull r00 = add2(add2(a00, p1[0]), p2[0]);
        ull r01 = add2(add2(a01, p1[1]), p2[1]);
        ull r10 = add2(add2(a10, p1[2]), p2[2]);
        ull r11 = add2(add2(a11, p1[3]), p2[3]);

        const float* xin_t = g_xin + s * (B * H);
        ull rr[2][2] = {{r00, r01}, {r10, r11}};
#pragma unroll
        for (int n = 0; n < 2; n++) {
            int i = ia + n;
#pragma unroll
            for (int q = 0; q < 2; q++) {
                float2 r = unpack2(rr[n][q]);
                int b = b0 + qt * 4 + 2 * q;
                float zp0 = zs[i * ZSTR + qt * 4 + 2 * q];
                float zp1 = zs[i * ZSTR + qt * 4 + 2 * q + 1];
                float v0 = v_update(g_v[b * H + i], r.x, xin_t[b * H + i], zp0);
                float v1 = v_update(g_v[(b + 1) * H + i], r.y, xin_t[(b + 1) * H + i], zp1);
                g_v[b * H + i] = v0;
                g_v[(b + 1) * H + i] = v1;
                znew[b * H + i] = (v0 > THRC) ? 1.0f : 0.0f;
                znew[(b + 1) * H + i] = (v1 > THRC) ? 1.0f : 0.0f;
            }
        }
    }
}

// ---------------- launch ----------------
extern "C" void kernel_launch(void* const* d_in, const int* in_sizes, int n_in,
                              void* d_out, int out_size) {
    const float* x     = (const float*)d_in[0];   // [T, B, D]
    const float* w_in  = (const float*)d_in[1];   // [H, D]
    const float* w_rec = (const float*)d_in[2];   // [H, H]
    const float* w_out = (const float*)d_in[3];   // [O, H]
    float* out = (float*)d_out;                   // [T, B, O]

    cudaFuncSetAttribute(k_fused, cudaFuncAttributeMaxDynamicSharedMemorySize, FUSED_SMEM);
    cudaFuncSetAttribute(k_gemm, cudaFuncAttributeMaxDynamicSharedMemorySize, 65536);

    k_init<<<(B * H + 255) / 256, 256>>>(out);
    k_prep_wt<<<dim3(H / 32, H / 32), dim3(32, 32)>>>(w_rec);
    // input GEMM: kc=400 panels, single launch (p0 stashed in smem)
    k_gemm<<<dim3(H / BN, (NSTEP * B) / BM), 256, 65536>>>(x, w_in);

    for (int s = 0; s <= NSTEP; s++) {
        k_fused<<<128, 768, FUSED_SMEM>>>(s, w_out, out);
    }
}